// round 4
// baseline (speedup 1.0000x reference)
#include <cuda_runtime.h>

#define HH 512
#define WW 512
#define CC 3
#define NB 4
#define ITERS 30
#define TILE 32
#define NELEM (NB * HH * WW * CC)
#define NBLK  1024u

__device__ float    g_buf0[NELEM];
__device__ float    g_buf1[NELEM];
__device__ double   g_sums[ITERS];
__device__ unsigned g_bar;

__device__ __forceinline__ int refl(int i, int n) {
    // np "reflect": -1 -> 1, n -> n-2
    if (i < 0) i = -i;
    if (i >= n) i = 2 * n - 2 - i;
    return i;
}

__global__ void zero_sums_kernel() {
    if (threadIdx.x < ITERS) g_sums[threadIdx.x] = 0.0;
    if (threadIdx.x == 0) g_bar = 0u;
}

// Persistent kernel: 1024 blocks, 7 blocks/SM x 148 SMs = 1036 capacity -> all
// blocks co-resident (single wave), so a software global barrier is safe.
// block: (32, 8); each block owns one 32x32 tile for all 30 iterations.
__global__ __launch_bounds__(256, 7) void rl_persist_kernel(
    const float* __restrict__ inputs,
    const float* __restrict__ k1g,
    const float* __restrict__ k2g,
    float* __restrict__ out,
    float* __restrict__ b0,
    float* __restrict__ b1)
{
    __shared__ float  s_lat[36][108];   // latent tile, halo 2
    __shared__ float  s_rb [34][102];   // inputs tile (halo 1), overwritten in-place by rb
    __shared__ float  s_k[54];          // [0:27) k1, [27:54) k2, layout (dy*3+dx)*3+ch
    __shared__ double s_red[8];
    __shared__ int    s_done;

    const int tx  = threadIdx.x;
    const int ty  = threadIdx.y;
    const int tid = ty * 32 + tx;
    const int n   = blockIdx.z;
    const int r0  = blockIdx.y * TILE;
    const int c0  = blockIdx.x * TILE;

    if (tid < 54) s_k[tid] = (tid < 27) ? k1g[tid] : k2g[tid - 27];
    if (tid == 0) s_done = 0;
    __syncthreads();

    const size_t img_off = (size_t)n * (HH * WW * CC);
    const float* in_img  = inputs + img_off;
    const bool xin2 = (c0 >= 2) && (c0 <= WW - TILE - 2);
    const bool xin1 = (c0 >= 1) && (c0 <= WW - TILE - 1);

    const float* cur = inputs;
    for (int it = 0; it < ITERS; it++) {
        float* nxt_base = (it == ITERS - 1) ? out : ((it & 1) ? b1 : b0);
        const float* lat_img = cur + img_off;
        float*       out_img = nxt_base + img_off;

        if (s_done) {
            // frozen: propagate latent through the ping-pong chain
            for (int y = ty; y < TILE; y += 8) {
                size_t base = ((size_t)(r0 + y) * WW + c0) * CC;
                for (int f = tx; f < TILE * CC; f += 32)
                    out_img[base + f] = lat_img[base + f];
            }
        } else {
            // ---- phase A: cooperative coalesced loads (latent halo2 + inputs halo1) ----
            for (int r = ty; r < 36; r += 8) {
                int gr = refl(r0 - 2 + r, HH);
                const float* rp = lat_img + (size_t)gr * (WW * CC);
                if (xin2) {
                    const float* p = rp + (c0 - 2) * CC;
                    s_lat[r][tx]      = p[tx];
                    s_lat[r][tx + 32] = p[tx + 32];
                    s_lat[r][tx + 64] = p[tx + 64];
                    if (tx < 12) s_lat[r][tx + 96] = p[tx + 96];
                } else {
                    for (int f = tx; f < 108; f += 32) {
                        int col = f / 3, ch = f - 3 * col;
                        int gc = refl(c0 - 2 + col, WW);
                        s_lat[r][f] = rp[gc * CC + ch];
                    }
                }
            }
            for (int r = ty; r < 34; r += 8) {
                int gr = refl(r0 - 1 + r, HH);
                const float* rp = in_img + (size_t)gr * (WW * CC);
                if (xin1) {
                    const float* p = rp + (c0 - 1) * CC;
                    s_rb[r][tx]      = p[tx];
                    s_rb[r][tx + 32] = p[tx + 32];
                    s_rb[r][tx + 64] = p[tx + 64];
                    if (tx < 6) s_rb[r][tx + 96] = p[tx + 96];
                } else {
                    for (int f = tx; f < 102; f += 32) {
                        int col = f / 3, ch = f - 3 * col;
                        int gc = refl(c0 - 1 + col, WW);
                        s_rb[r][f] = rp[gc * CC + ch];
                    }
                }
            }
            __syncthreads();

            // ---- stage 1: est = conv(lat,k1); rb = in/est (in-place in s_rb), 34x34 ----
            if (ty < 7) {
                const int y0   = ty * 5;
                const int yend = min(y0 + 5, 34);
                #pragma unroll
                for (int ch = 0; ch < 3; ch++) {
                    const float kk0 = s_k[ch],      kk1 = s_k[3 + ch],  kk2 = s_k[6 + ch];
                    const float kk3 = s_k[9 + ch],  kk4 = s_k[12 + ch], kk5 = s_k[15 + ch];
                    const float kk6 = s_k[18 + ch], kk7 = s_k[21 + ch], kk8 = s_k[24 + ch];
                    const int xc = tx * 3 + ch;
                    float a0 = s_lat[y0][xc],     a1 = s_lat[y0][xc + 3],     a2 = s_lat[y0][xc + 6];
                    float b0r = s_lat[y0 + 1][xc], b1r = s_lat[y0 + 1][xc + 3], b2r = s_lat[y0 + 1][xc + 6];
                    for (int y = y0; y < yend; y++) {
                        float v0 = s_lat[y + 2][xc], v1 = s_lat[y + 2][xc + 3], v2 = s_lat[y + 2][xc + 6];
                        float est = a0 * kk0;
                        est = fmaf(a1, kk1, est); est = fmaf(a2, kk2, est);
                        est = fmaf(b0r, kk3, est); est = fmaf(b1r, kk4, est);
                        est = fmaf(b2r, kk5, est); est = fmaf(v0, kk6, est);
                        est = fmaf(v1, kk7, est); est = fmaf(v2, kk8, est);
                        float inp = s_rb[y][xc];
                        s_rb[y][xc] = __fdividef(inp, est);
                        a0 = b0r; a1 = b1r; a2 = b2r;
                        b0r = v0; b1r = v1; b2r = v2;
                    }
                }
            } else {
                // warp 7: rb columns x = 32,33 for all 34 rows
                for (int idx = tx; idx < 68; idx += 32) {
                    int x = 32 + (idx & 1);
                    int y = idx >> 1;
                    int xc = x * 3;
                    #pragma unroll
                    for (int ch = 0; ch < 3; ch++) {
                        float est = 0.f;
                        #pragma unroll
                        for (int dy = 0; dy < 3; dy++)
                            #pragma unroll
                            for (int dx = 0; dx < 3; dx++)
                                est = fmaf(s_lat[y + dy][xc + dx * 3 + ch],
                                           s_k[(dy * 3 + dx) * 3 + ch], est);
                        float inp = s_rb[y][xc + ch];
                        s_rb[y][xc + ch] = __fdividef(inp, est);
                    }
                }
            }
            __syncthreads();

            // ---- stage 2: e = conv(rb,k2); out = lat*e, 32x32 ----
            float fsum = 0.f;
            {
                const int y0 = ty * 4;
                #pragma unroll
                for (int ch = 0; ch < 3; ch++) {
                    const float kk0 = s_k[27 + ch], kk1 = s_k[30 + ch], kk2 = s_k[33 + ch];
                    const float kk3 = s_k[36 + ch], kk4 = s_k[39 + ch], kk5 = s_k[42 + ch];
                    const float kk6 = s_k[45 + ch], kk7 = s_k[48 + ch], kk8 = s_k[51 + ch];
                    const int xc = tx * 3 + ch;
                    float a0 = s_rb[y0][xc],     a1 = s_rb[y0][xc + 3],     a2 = s_rb[y0][xc + 6];
                    float b0r = s_rb[y0 + 1][xc], b1r = s_rb[y0 + 1][xc + 3], b2r = s_rb[y0 + 1][xc + 6];
                    #pragma unroll
                    for (int k = 0; k < 4; k++) {
                        int y = y0 + k;
                        float v0 = s_rb[y + 2][xc], v1 = s_rb[y + 2][xc + 3], v2 = s_rb[y + 2][xc + 6];
                        float e = a0 * kk0;
                        e = fmaf(a1, kk1, e); e = fmaf(a2, kk2, e);
                        e = fmaf(b0r, kk3, e); e = fmaf(b1r, kk4, e);
                        e = fmaf(b2r, kk5, e); e = fmaf(v0, kk6, e);
                        e = fmaf(v1, kk7, e); e = fmaf(v2, kk8, e);
                        fsum += e;
                        float lat = s_lat[y + 2][(tx + 2) * 3 + ch];
                        out_img[((size_t)(r0 + y) * WW + (c0 + tx)) * CC + ch] = lat * e;
                        a0 = b0r; a1 = b1r; a2 = b2r;
                        b0r = v0; b1r = v1; b2r = v2;
                    }
                }
            }

            // ---- block reduction -> one double atomic ----
            #pragma unroll
            for (int off = 16; off > 0; off >>= 1)
                fsum += __shfl_down_sync(0xffffffffu, fsum, off);
            if (tx == 0) s_red[ty] = (double)fsum;
            __syncthreads();
            if (tid == 0) {
                double v = 0.0;
                #pragma unroll
                for (int i = 0; i < 8; i++) v += s_red[i];
                atomicAdd(&g_sums[it], v);
            }
        }

        // ---- global barrier between iterations (monotonic cumulative counter) ----
        if (it < ITERS - 1) {
            __syncthreads();
            if (tid == 0) {
                __threadfence();
                unsigned target = (unsigned)(it + 1) * NBLK;
                unsigned prev = atomicAdd(&g_bar, 1u);
                if (prev + 1u < target) {
                    volatile unsigned* p = &g_bar;
                    while (*p < target) __nanosleep(64);
                }
                __threadfence();
                // update freeze latch from this iteration's sum
                double d = fabs(1.0 - g_sums[it] * (1.0 / (double)NELEM));
                if (d < 1e-5) s_done = 1;
            }
            __syncthreads();
        }
        cur = nxt_base;
    }
}

extern "C" void kernel_launch(void* const* d_in, const int* in_sizes, int n_in,
                              void* d_out, int out_size) {
    const float* inputs = (const float*)d_in[0];
    const float* k1     = (const float*)d_in[1];
    const float* k2     = (const float*)d_in[2];
    float* out = (float*)d_out;

    float *b0 = nullptr, *b1 = nullptr;
    cudaGetSymbolAddress((void**)&b0, g_buf0);
    cudaGetSymbolAddress((void**)&b1, g_buf1);

    zero_sums_kernel<<<1, 32>>>();

    dim3 blk(32, 8, 1);
    dim3 grid(WW / TILE, HH / TILE, NB);   // 16 x 16 x 4 = 1024 blocks, one wave
    rl_persist_kernel<<<grid, blk>>>(inputs, k1, k2, out, b0, b1);
}